// round 1
// baseline (speedup 1.0000x reference)
#include <cuda_runtime.h>
#include <math.h>
#include <stdint.h>

#define NSAMP   32768
#define NSIG    16          // 8 target + 8 recon
#define NBANDS  7
#define NFILT   64
#define KTOP    128
#define BAND_SPAN 65024     // sum of band sizes per signal
#define PBLOCKS 56

// ---------------- scratch (static device globals; no allocation) -------------
__device__ float2 d_X[NSIG * 16384];                 // rfft bins 0..16383 per signal
__device__ float  d_band[NSIG * BAND_SPAN];          // all band time signals
__device__ float  d_seg [NSIG * NBANDS * NFILT * 65];// segment maxima (65 segs)
__device__ float  d_tkv [NSIG * NBANDS * KTOP];      // top-k values
__device__ int    d_tki [NSIG * NBANDS * KTOP];      // top-k flat indices
__device__ float  d_partial[PBLOCKS];

__device__ __forceinline__ int band_off(int j) { return 512 * ((1 << j) - 1); }

// ---------------- in-place radix-2 DIT FFT over smem -------------------------
// data already bit-reverse permuted. tw[r] = (cos, sin)(2*pi*r/n), r < n/2.
// sign = -1 forward (e^{-i}), +1 inverse (e^{+i}).
__device__ __forceinline__ void fft_inplace(float2* a, const float2* tw,
                                            int n, int logn, float sign,
                                            int tid, int T) {
    int nb = n >> 1;
    for (int st = 1; st <= logn; st++) {
        int half  = 1 << (st - 1);
        int shift = logn - st;
        for (int idx = tid; idx < nb; idx += T) {
            int jj = idx & (half - 1);
            int i0 = ((idx >> (st - 1)) << st) + jj;
            int i1 = i0 + half;
            float2 w = tw[jj << shift];
            float wy = sign * w.y;
            float2 u = a[i0], v = a[i1];
            float vr = v.x * w.x - v.y * wy;
            float vi = v.x * wy + v.y * w.x;
            a[i0] = make_float2(u.x + vr, u.y + vi);
            a[i1] = make_float2(u.x - vr, u.y - vi);
        }
        __syncthreads();
    }
}

__device__ __forceinline__ void build_twiddles(float2* tw, int n, int tid, int T) {
    for (int r = tid; r < (n >> 1); r += T) {
        float s_, c_;
        sincospif(2.0f * (float)r / (float)n, &s_, &c_);
        tw[r] = make_float2(c_, s_);
    }
}

// ---------------- 1) forward rfft of each 32768-sample signal -----------------
extern __shared__ float2 smem_c[];

__global__ __launch_bounds__(512) void fwd_fft_kernel(const float* __restrict__ tgt,
                                                      const float* __restrict__ rec) {
    const int m = 16384, logm = 14;
    int sig = blockIdx.x;
    const float* x = (sig < 8) ? (tgt + (size_t)sig * NSAMP)
                               : (rec + (size_t)(sig - 8) * NSAMP);
    float2* data = smem_c;
    float2* tw   = smem_c + m;
    int tid = threadIdx.x, T = blockDim.x;

    build_twiddles(tw, m, tid, T);
    for (int t = tid; t < m; t += T) {
        int r = (int)(__brev((unsigned)t) >> (32 - logm));
        data[r] = make_float2(x[2 * t], x[2 * t + 1]);
    }
    __syncthreads();
    fft_inplace(data, tw, m, logm, -1.0f, tid, T);

    // untangle: X[k] = E + e^{-2pi i k/N} * (-i) * D
    for (int k = tid; k < m; k += T) {
        float2 zk = data[k];
        float2 zm = data[(m - k) & (m - 1)];
        float2 E = make_float2(0.5f * (zk.x + zm.x), 0.5f * (zk.y - zm.y));
        float2 D = make_float2(0.5f * (zk.x - zm.x), 0.5f * (zk.y + zm.y));
        float s_, c_;
        sincospif(-2.0f * (float)k / (float)NSAMP, &s_, &c_);
        float2 miD = make_float2(D.y, -D.x);                 // (-i)*D
        float tr = miD.x * c_ - miD.y * s_;
        float ti = miD.x * s_ + miD.y * c_;
        d_X[sig * 16384 + k] = make_float2(E.x + tr, E.y + ti);
    }
}

// ---------------- 2) per-band inverse rfft (ortho-scaled) ---------------------
__global__ __launch_bounds__(512) void inv_band_kernel() {
    int j   = blockIdx.x;              // band
    int sig = blockIdx.y;
    int m = 256 << j, logm = 8 + j;
    int lo = (j == 0) ? 0 : (m >> 1);
    int s2 = 2 * m;
    const float2* X = d_X + sig * 16384;
    float2* data = smem_c;
    float2* tw   = smem_c + m;
    int tid = threadIdx.x, T = blockDim.x;

    build_twiddles(tw, m, tid, T);
    for (int k = tid; k < m; k += T) {
        float2 Xk = (k >= lo) ? X[k] : make_float2(0.f, 0.f);
        int mk = m - k;
        float2 Xm = (mk >= lo && mk < m) ? X[mk] : make_float2(0.f, 0.f);
        float2 E = make_float2(0.5f * (Xk.x + Xm.x), 0.5f * (Xk.y - Xm.y));
        float2 D = make_float2(0.5f * (Xk.x - Xm.x), 0.5f * (Xk.y + Xm.y));
        float s_, c_;
        sincospif(2.0f * (float)k / (float)s2, &s_, &c_);
        float2 O = make_float2(D.x * c_ - D.y * s_, D.x * s_ + D.y * c_);
        float2 Z = make_float2(E.x - O.y, E.y + O.x);        // E + i*O
        int r = (int)(__brev((unsigned)k) >> (32 - logm));
        data[r] = Z;
    }
    __syncthreads();
    fft_inplace(data, tw, m, logm, +1.0f, tid, T);

    float scale = 2.0f * rsqrtf((float)s2 * (float)NSAMP);
    float* out = d_band + sig * BAND_SPAN + band_off(j);
    for (int t = tid; t < m; t += T) {
        float2 z = data[t];
        out[2 * t]     = scale * z.x;
        out[2 * t + 1] = scale * z.y;
    }
}

// ---------------- 3) 64-tap FIR + segment maxima (conv computed once) ---------
__global__ __launch_bounds__(256) void conv_seg_kernel(const float* __restrict__ filters) {
    int q   = blockIdx.x;   // 0..64 segment
    int j   = blockIdx.y;   // band
    int sig = blockIdx.z;
    int stride = 8 << j;
    int s = 512 << j;
    int pad = stride >> 1;
    int i0 = q * stride - pad;
    int i1 = i0 + stride;
    const float* band = d_band + sig * BAND_SPAN + band_off(j);

    __shared__ float tile[512 + 64];
    __shared__ float filt[64 * 65];
    __shared__ float red[4][64];

    int tid = threadIdx.x;
    int tstart = i0 - 63;
    int tlen = stride + 63;
    for (int t = tid; t < tlen; t += 256) {
        int g = tstart + t;
        tile[t] = (g >= 0 && g < s) ? band[g] : 0.0f;
    }
    for (int t = tid; t < 4096; t += 256)
        filt[(t >> 6) * 65 + (t & 63)] = filters[t];
    __syncthreads();

    int f = tid & 63, grp = tid >> 6;
    float taps[64];
#pragma unroll
    for (int k = 0; k < 64; k++) taps[k] = filt[f * 65 + k];

    float mx = -INFINITY;
    for (int i = i0 + grp; i < i1; i += 4) {
        if (i < 0 || i >= s) continue;
        int li = i - tstart;
        float acc = 0.0f;
#pragma unroll
        for (int k = 0; k < 64; k++) acc = fmaf(taps[k], tile[li - k], acc);
        mx = fmaxf(mx, acc);
    }
    red[grp][f] = mx;
    __syncthreads();
    if (tid < 64) {
        float v = fmaxf(fmaxf(red[0][tid], red[1][tid]),
                        fmaxf(red[2][tid], red[3][tid]));
        d_seg[((sig * NBANDS + j) * NFILT + tid) * 65 + q] = v;
    }
}

// ---------------- 4) exact top-128 (desc value, asc index) --------------------
__global__ __launch_bounds__(512) void topk_kernel() {
    int j   = blockIdx.x;
    int sig = blockIdx.y;
    __shared__ unsigned long long keys[4096];
    const float* seg = d_seg + (size_t)(sig * NBANDS + j) * NFILT * 65;
    int tid = threadIdx.x, T = blockDim.x;

    for (int t = tid; t < 4096; t += T) {
        int f = t >> 6, o = t & 63;
        float v = fmaxf(seg[f * 65 + o], seg[f * 65 + o + 1]);  // pooled
        unsigned ub = __float_as_uint(v);
        ub = (ub >> 31) ? ~ub : (ub | 0x80000000u);  // ascending-order map
        unsigned hk = ~ub;                           // descending value
        keys[t] = ((unsigned long long)hk << 32) | (unsigned)t;
    }
    __syncthreads();
    for (int kk = 2; kk <= 4096; kk <<= 1) {
        for (int jj = kk >> 1; jj > 0; jj >>= 1) {
            for (int t = tid; t < 4096; t += T) {
                int ixj = t ^ jj;
                if (ixj > t) {
                    bool up = ((t & kk) == 0);
                    unsigned long long A = keys[t], B = keys[ixj];
                    if (up ? (A > B) : (A < B)) { keys[t] = B; keys[ixj] = A; }
                }
            }
            __syncthreads();
        }
    }
    if (tid < KTOP) {
        unsigned long long key = keys[tid];
        int idx = (int)(unsigned)key;
        int f = idx >> 6, o = idx & 63;
        float v = fmaxf(seg[f * 65 + o], seg[f * 65 + o + 1]);
        int base = (sig * NBANDS + j) * KTOP + tid;
        d_tkv[base] = v;
        d_tki[base] = idx;
    }
}

// ---------------- 5) loss: gather projections, |t-r| partial sums -------------
__global__ __launch_bounds__(128) void loss_kernel(const float* __restrict__ PT,
                                                   const float* __restrict__ PF) {
    int b = blockIdx.x;   // batch 0..7
    int j = blockIdx.y;   // band
    int k = threadIdx.x;  // 0..127
    int ti = (b * NBANDS + j) * KTOP + k;
    int ri = ((b + 8) * NBANDS + j) * KTOP + k;
    float vt = d_tkv[ti]; int it = d_tki[ti];
    float vr = d_tkv[ri]; int ir = d_tki[ri];
    int tmt = it & 63, cht = it >> 6;
    int tmr = ir & 63, chr_ = ir >> 6;
    const float* ptt = PT + tmt * 128;
    const float* ptr_ = PT + tmr * 128;
    const float* pft = PF + cht * 128;
    const float* pfr = PF + chr_ * 128;
    float ssum = 0.0f;
#pragma unroll 4
    for (int d = 0; d < 128; d++) {
        ssum += fabsf(vt * ptt[d] - vr * ptr_[d]);
        ssum += fabsf(pft[d] - pfr[d]);
    }
    __shared__ float rs[128];
    rs[k] = ssum;
    __syncthreads();
    for (int st = 64; st > 0; st >>= 1) {
        if (k < st) rs[k] += rs[k + st];
        __syncthreads();
    }
    if (k == 0) d_partial[b * NBANDS + j] = rs[0];
}

__global__ void final_kernel(float* out) {
    if (threadIdx.x == 0) {
        float s = 0.0f;
        for (int i = 0; i < PBLOCKS; i++) s += d_partial[i];
        out[0] = s / 1835008.0f;   // 8 * 128 * 256 * 7
    }
}

// ---------------- launch ------------------------------------------------------
extern "C" void kernel_launch(void* const* d_in, const int* in_sizes, int n_in,
                              void* d_out, int out_size) {
    const float* target  = (const float*)d_in[0];
    const float* recon   = (const float*)d_in[1];
    const float* filters = (const float*)d_in[2];
    const float* PT      = (const float*)d_in[3];
    const float* PF      = (const float*)d_in[4];
    float* out = (float*)d_out;

    const int FWD_SMEM = (16384 + 8192) * sizeof(float2);   // 196608 B
    cudaFuncSetAttribute(fwd_fft_kernel,
                         cudaFuncAttributeMaxDynamicSharedMemorySize, FWD_SMEM);
    cudaFuncSetAttribute(inv_band_kernel,
                         cudaFuncAttributeMaxDynamicSharedMemorySize, FWD_SMEM);

    fwd_fft_kernel<<<NSIG, 512, FWD_SMEM>>>(target, recon);
    inv_band_kernel<<<dim3(NBANDS, NSIG), 512, FWD_SMEM>>>();
    conv_seg_kernel<<<dim3(65, NBANDS, NSIG), 256>>>(filters);
    topk_kernel<<<dim3(NBANDS, NSIG), 512>>>();
    loss_kernel<<<dim3(8, NBANDS), 128>>>(PT, PF);
    final_kernel<<<1, 32>>>(out);
}

// round 2
// speedup vs baseline: 1.6244x; 1.6244x over previous
#include <cuda_runtime.h>
#include <math.h>
#include <stdint.h>

#define NSAMP   32768
#define NSIG    16          // 8 target + 8 recon
#define NBANDS  7
#define NFILT   64
#define KTOP    128
#define BAND_SPAN 65024     // sum of band sizes per signal
#define PBLOCKS 56

// ---------------- scratch (static device globals; no allocation) -------------
__device__ float2 d_X[NSIG * 16384];                 // rfft bins 0..16383 per signal
__device__ float  d_band[NSIG * BAND_SPAN];          // all band time signals
__device__ float  d_seg [NSIG * NBANDS * NFILT * 65];// segment maxima (65 segs)
__device__ float  d_tkv [NSIG * NBANDS * KTOP];      // top-k values
__device__ int    d_tki [NSIG * NBANDS * KTOP];      // top-k flat indices
__device__ float  d_partial[PBLOCKS];

__device__ __forceinline__ int band_off(int j) { return 512 * ((1 << j) - 1); }

// ---------------- in-place radix-2 DIT FFT over smem -------------------------
__device__ __forceinline__ void fft_inplace(float2* a, const float2* tw,
                                            int n, int logn, float sign,
                                            int tid, int T) {
    int nb = n >> 1;
    for (int st = 1; st <= logn; st++) {
        int half  = 1 << (st - 1);
        int shift = logn - st;
        for (int idx = tid; idx < nb; idx += T) {
            int jj = idx & (half - 1);
            int i0 = ((idx >> (st - 1)) << st) + jj;
            int i1 = i0 + half;
            float2 w = tw[jj << shift];
            float wy = sign * w.y;
            float2 u = a[i0], v = a[i1];
            float vr = v.x * w.x - v.y * wy;
            float vi = v.x * wy + v.y * w.x;
            a[i0] = make_float2(u.x + vr, u.y + vi);
            a[i1] = make_float2(u.x - vr, u.y - vi);
        }
        __syncthreads();
    }
}

__device__ __forceinline__ void build_twiddles(float2* tw, int n, int tid, int T) {
    for (int r = tid; r < (n >> 1); r += T) {
        float s_, c_;
        sincospif(2.0f * (float)r / (float)n, &s_, &c_);
        tw[r] = make_float2(c_, s_);
    }
}

// ---------------- 1) forward rfft of each 32768-sample signal -----------------
extern __shared__ float2 smem_c[];

__global__ __launch_bounds__(1024) void fwd_fft_kernel(const float* __restrict__ tgt,
                                                       const float* __restrict__ rec) {
    const int m = 16384, logm = 14;
    int sig = blockIdx.x;
    const float* x = (sig < 8) ? (tgt + (size_t)sig * NSAMP)
                               : (rec + (size_t)(sig - 8) * NSAMP);
    float2* data = smem_c;
    float2* tw   = smem_c + m;
    int tid = threadIdx.x, T = blockDim.x;

    build_twiddles(tw, m, tid, T);
    for (int t = tid; t < m; t += T) {
        int r = (int)(__brev((unsigned)t) >> (32 - logm));
        data[r] = make_float2(x[2 * t], x[2 * t + 1]);
    }
    __syncthreads();
    fft_inplace(data, tw, m, logm, -1.0f, tid, T);

    for (int k = tid; k < m; k += T) {
        float2 zk = data[k];
        float2 zm = data[(m - k) & (m - 1)];
        float2 E = make_float2(0.5f * (zk.x + zm.x), 0.5f * (zk.y - zm.y));
        float2 D = make_float2(0.5f * (zk.x - zm.x), 0.5f * (zk.y + zm.y));
        float s_, c_;
        sincospif(-2.0f * (float)k / (float)NSAMP, &s_, &c_);
        float2 miD = make_float2(D.y, -D.x);
        float tr = miD.x * c_ - miD.y * s_;
        float ti = miD.x * s_ + miD.y * c_;
        d_X[sig * 16384 + k] = make_float2(E.x + tr, E.y + ti);
    }
}

// ---------------- 2) per-band inverse rfft (ortho-scaled) ---------------------
__global__ __launch_bounds__(1024) void inv_band_kernel() {
    int j   = blockIdx.x;
    int sig = blockIdx.y;
    int m = 256 << j, logm = 8 + j;
    int lo = (j == 0) ? 0 : (m >> 1);
    int s2 = 2 * m;
    const float2* X = d_X + sig * 16384;
    float2* data = smem_c;
    float2* tw   = smem_c + m;
    int tid = threadIdx.x, T = blockDim.x;

    build_twiddles(tw, m, tid, T);
    for (int k = tid; k < m; k += T) {
        float2 Xk = (k >= lo) ? X[k] : make_float2(0.f, 0.f);
        int mk = m - k;
        float2 Xm = (mk >= lo && mk < m) ? X[mk] : make_float2(0.f, 0.f);
        float2 E = make_float2(0.5f * (Xk.x + Xm.x), 0.5f * (Xk.y - Xm.y));
        float2 D = make_float2(0.5f * (Xk.x - Xm.x), 0.5f * (Xk.y + Xm.y));
        float s_, c_;
        sincospif(2.0f * (float)k / (float)s2, &s_, &c_);
        float2 O = make_float2(D.x * c_ - D.y * s_, D.x * s_ + D.y * c_);
        float2 Z = make_float2(E.x - O.y, E.y + O.x);
        int r = (int)(__brev((unsigned)k) >> (32 - logm));
        data[r] = Z;
    }
    __syncthreads();
    fft_inplace(data, tw, m, logm, +1.0f, tid, T);

    float scale = 2.0f * rsqrtf((float)s2 * (float)NSAMP);
    float* out = d_band + sig * BAND_SPAN + band_off(j);
    for (int t = tid; t < m; t += T) {
        float2 z = data[t];
        out[2 * t]     = scale * z.x;
        out[2 * t + 1] = scale * z.y;
    }
}

// ---------------- 3) 64-tap FIR + segment maxima, packed f32x2 ----------------
#define FMA2(acc, a, b) asm("fma.rn.f32x2 %0, %1, %2, %3;" \
    : "=l"(acc) : "l"(a), "l"(b), "l"(acc))

// Computes max over 2P consecutive conv outputs starting at 'base' (even).
// S[p] accumulates even-tap terms, T[p] odd-tap terms; both use ALIGNED float2
// operands from the sliding window W. Cross-combine happens once at the end.
template<int P>
__device__ __forceinline__ float conv_block(const unsigned long long* __restrict__ tilU,
                                            const unsigned long long* __restrict__ frowU,
                                            int rel, int base, int s) {
    unsigned long long W[P + 1], S[P], T[P + 1];
#pragma unroll
    for (int m = 0; m <= P; m++) W[m] = tilU[rel - 1 + m];
#pragma unroll
    for (int p = 0; p < P; p++) S[p] = 0ull;
#pragma unroll
    for (int p = 0; p <= P; p++) T[p] = 0ull;
#pragma unroll
    for (int h = 0; h < 32; h++) {
        unsigned long long te = frowU[2 * h];
        unsigned long long to = frowU[2 * h + 1];
#pragma unroll
        for (int p = 0; p < P; p++) FMA2(S[p], W[p + 1], te);
#pragma unroll
        for (int p = 0; p <= P; p++) FMA2(T[p], W[p], to);
        if (h < 31) {
#pragma unroll
            for (int m = P; m >= 1; m--) W[m] = W[m - 1];
            W[0] = tilU[rel - h - 2];
        }
    }
    float mx = -INFINITY;
#pragma unroll
    for (int p = 0; p < P; p++) {
        float2 sv = *(float2*)&S[p];
        float2 ta = *(float2*)&T[p];
        float2 tb = *(float2*)&T[p + 1];
        float v0 = sv.x + ta.y;        // out[base+2p]
        float v1 = sv.y + tb.x;        // out[base+2p+1]
        int ia = base + 2 * p;
        if (ia < 0 || ia >= s)         v0 = -INFINITY;
        if (ia + 1 < 0 || ia + 1 >= s) v1 = -INFINITY;
        mx = fmaxf(mx, fmaxf(v0, v1));
    }
    return mx;
}

__global__ __launch_bounds__(256) void conv_seg_kernel(const float* __restrict__ filters) {
    int q   = blockIdx.x;   // 0..64 segment
    int j   = blockIdx.y;   // band
    int sig = blockIdx.z;
    int stride = 8 << j;
    int s = 512 << j;
    int pad = stride >> 1;
    int i0 = q * stride - pad;
    const float* band = d_band + sig * BAND_SPAN + band_off(j);

    __shared__ float2 tile2[288];
    __shared__ float2 filt2[64 * 65];
    __shared__ float red[4][64];

    int tid = threadIdx.x;
    int tstart2 = i0 - 64;                    // even
    int tlen2 = (stride + 64) >> 1;
    for (int m = tid; m < tlen2; m += 256) {
        int g = tstart2 + 2 * m;
        float a = (g >= 0 && g < s)         ? band[g]     : 0.0f;
        float b = (g + 1 >= 0 && g + 1 < s) ? band[g + 1] : 0.0f;
        tile2[m] = make_float2(a, b);
    }
    for (int t = tid; t < 4096; t += 256) {
        float v = filters[t];
        filt2[(t >> 6) * 65 + (t & 63)] = make_float2(v, v);  // pre-duplicated taps
    }
    __syncthreads();

    int f = tid & 63, grp = tid >> 6;
    const unsigned long long* tilU  = (const unsigned long long*)tile2;
    const unsigned long long* frowU = (const unsigned long long*)(filt2 + f * 65);
    int spt   = stride >> 2;                  // samples per thread (even, >=2)
    int base0 = i0 + grp * spt;
    int rel0  = grp * (spt >> 1) + 32;

    float mx;
    if (j == 0)      mx = conv_block<1>(tilU, frowU, rel0, base0, s);
    else if (j == 1) mx = conv_block<2>(tilU, frowU, rel0, base0, s);
    else {
        mx = -INFINITY;
        int nblk = spt >> 3;
        for (int blk = 0; blk < nblk; blk++)
            mx = fmaxf(mx, conv_block<4>(tilU, frowU, rel0 + 4 * blk,
                                         base0 + 8 * blk, s));
    }
    red[grp][f] = mx;
    __syncthreads();
    if (tid < 64) {
        float v = fmaxf(fmaxf(red[0][tid], red[1][tid]),
                        fmaxf(red[2][tid], red[3][tid]));
        d_seg[((sig * NBANDS + j) * NFILT + tid) * 65 + q] = v;
    }
}

// ---------------- 4) exact top-128 via radix-select + small bitonic -----------
__global__ __launch_bounds__(256) void topk_kernel() {
    int j   = blockIdx.x;
    int sig = blockIdx.y;
    __shared__ unsigned hk[4096];
    __shared__ int hist[4096];
    __shared__ unsigned long long cand[1024];
    __shared__ int scanbuf[256];
    __shared__ int s_b1, s_count;
    const float* seg = d_seg + (size_t)(sig * NBANDS + j) * NFILT * 65;
    int tid = threadIdx.x;

    // keys: smaller hk = larger pooled value (exact desc order)
    for (int t = tid; t < 4096; t += 256) {
        int f = t >> 6, o = t & 63;
        float v = fmaxf(seg[f * 65 + o], seg[f * 65 + o + 1]);
        unsigned ub = __float_as_uint(v);
        ub = (ub >> 31) ? ~ub : (ub | 0x80000000u);
        hk[t] = ~ub;
        hist[t] = 0;
    }
    if (tid == 0) s_count = 0;
    __syncthreads();
    for (int t = tid; t < 4096; t += 256)
        atomicAdd(&hist[hk[t] >> 20], 1);
    __syncthreads();

    // find bucket b1 where cumulative count crosses 128
    int part = 0;
#pragma unroll
    for (int i = 0; i < 16; i++) part += hist[tid * 16 + i];
    scanbuf[tid] = part;
    __syncthreads();
    for (int off = 1; off < 256; off <<= 1) {
        int v = (tid >= off) ? scanbuf[tid - off] : 0;
        __syncthreads();
        scanbuf[tid] += v;
        __syncthreads();
    }
    int incl = scanbuf[tid];
    int excl = (tid > 0) ? scanbuf[tid - 1] : 0;
    if (incl >= KTOP && excl < KTOP) {
        int cum = excl;
        for (int i = 0; i < 16; i++) {
            int c = hist[tid * 16 + i];
            if (cum + c >= KTOP) { s_b1 = tid * 16 + i; break; }
            cum += c;
        }
    }
    __syncthreads();
    unsigned b1 = (unsigned)s_b1;

    // gather candidates (everything at or above bucket b1)
    for (int t = tid; t < 4096; t += 256) {
        if ((hk[t] >> 20) <= b1) {
            int pos = atomicAdd(&s_count, 1);
            if (pos < 1024)
                cand[pos] = ((unsigned long long)hk[t] << 32) | (unsigned)t;
        }
    }
    __syncthreads();
    int n = s_count < 1024 ? s_count : 1024;
    for (int t = tid; t < 1024; t += 256)
        if (t >= n) cand[t] = ~0ull;
    __syncthreads();

    // bitonic sort 1024 ascending
    for (int kk = 2; kk <= 1024; kk <<= 1) {
        for (int jj = kk >> 1; jj > 0; jj >>= 1) {
            for (int v = tid; v < 1024; v += 256) {
                int ixj = v ^ jj;
                if (ixj > v) {
                    bool up = ((v & kk) == 0);
                    unsigned long long A = cand[v], B = cand[ixj];
                    if (up ? (A > B) : (A < B)) { cand[v] = B; cand[ixj] = A; }
                }
            }
            __syncthreads();
        }
    }
    if (tid < KTOP) {
        unsigned long long key = cand[tid];
        int idx = (int)(unsigned)key;
        int f = idx >> 6, o = idx & 63;
        float v = fmaxf(seg[f * 65 + o], seg[f * 65 + o + 1]);
        int base = (sig * NBANDS + j) * KTOP + tid;
        d_tkv[base] = v;
        d_tki[base] = idx;
    }
}

// ---------------- 5) loss ------------------------------------------------------
__global__ __launch_bounds__(128) void loss_kernel(const float* __restrict__ PT,
                                                   const float* __restrict__ PF) {
    int b = blockIdx.x;
    int j = blockIdx.y;
    int k = threadIdx.x;
    int ti = (b * NBANDS + j) * KTOP + k;
    int ri = ((b + 8) * NBANDS + j) * KTOP + k;
    float vt = d_tkv[ti]; int it = d_tki[ti];
    float vr = d_tkv[ri]; int ir = d_tki[ri];
    int tmt = it & 63, cht = it >> 6;
    int tmr = ir & 63, chr_ = ir >> 6;
    const float* ptt  = PT + tmt * 128;
    const float* ptr_ = PT + tmr * 128;
    const float* pft  = PF + cht * 128;
    const float* pfr  = PF + chr_ * 128;
    float ssum = 0.0f;
#pragma unroll 4
    for (int d = 0; d < 128; d++) {
        ssum += fabsf(vt * ptt[d] - vr * ptr_[d]);
        ssum += fabsf(pft[d] - pfr[d]);
    }
    __shared__ float rs[128];
    rs[k] = ssum;
    __syncthreads();
    for (int st = 64; st > 0; st >>= 1) {
        if (k < st) rs[k] += rs[k + st];
        __syncthreads();
    }
    if (k == 0) d_partial[b * NBANDS + j] = rs[0];
}

__global__ void final_kernel(float* out) {
    if (threadIdx.x == 0) {
        float s = 0.0f;
        for (int i = 0; i < PBLOCKS; i++) s += d_partial[i];
        out[0] = s / 1835008.0f;   // 8 * 128 * 256 * 7
    }
}

// ---------------- launch ------------------------------------------------------
extern "C" void kernel_launch(void* const* d_in, const int* in_sizes, int n_in,
                              void* d_out, int out_size) {
    const float* target  = (const float*)d_in[0];
    const float* recon   = (const float*)d_in[1];
    const float* filters = (const float*)d_in[2];
    const float* PT      = (const float*)d_in[3];
    const float* PF      = (const float*)d_in[4];
    float* out = (float*)d_out;

    const int FWD_SMEM = (16384 + 8192) * sizeof(float2);   // 196608 B
    cudaFuncSetAttribute(fwd_fft_kernel,
                         cudaFuncAttributeMaxDynamicSharedMemorySize, FWD_SMEM);
    cudaFuncSetAttribute(inv_band_kernel,
                         cudaFuncAttributeMaxDynamicSharedMemorySize, FWD_SMEM);

    fwd_fft_kernel<<<NSIG, 1024, FWD_SMEM>>>(target, recon);
    inv_band_kernel<<<dim3(NBANDS, NSIG), 1024, FWD_SMEM>>>();
    conv_seg_kernel<<<dim3(65, NBANDS, NSIG), 256>>>(filters);
    topk_kernel<<<dim3(NBANDS, NSIG), 256>>>();
    loss_kernel<<<dim3(8, NBANDS), 128>>>(PT, PF);
    final_kernel<<<1, 32>>>(out);
}

// round 3
// speedup vs baseline: 2.3797x; 1.4650x over previous
#include <cuda_runtime.h>
#include <math.h>
#include <stdint.h>

#define NSAMP   32768
#define NSIG    16          // 8 target + 8 recon
#define NBANDS  7
#define NFILT   64
#define KTOP    128
#define BAND_SPAN 65024     // sum of band sizes per signal
#define PBLOCKS 56

// multi-scale padding: conflict-free strided smem access for all FFT stages
#define PADI(i) ((i) + ((i) >> 4) + ((i) >> 8))

// ---------------- scratch (static device globals; no allocation) -------------
__device__ float2 d_X[NSIG * 16384];                 // rfft bins 0..16383 per signal
__device__ float  d_band[NSIG * BAND_SPAN];          // all band time signals
__device__ float  d_seg [NSIG * NBANDS * NFILT * 65];// segment maxima (65 segs)
__device__ float  d_tkv [NSIG * NBANDS * KTOP];      // top-k values
__device__ int    d_tki [NSIG * NBANDS * KTOP];      // top-k flat indices
__device__ float  d_partial[PBLOCKS];

__device__ __forceinline__ int band_off(int j) { return 512 * ((1 << j) - 1); }

__device__ __forceinline__ float2 cmul_s(float2 a, float2 w, float sign) {
    float wy = sign * w.y;
    return make_float2(a.x * w.x - a.y * wy, a.x * wy + a.y * w.x);
}

// ------------- fused radix-4 (2x radix-2) in-place DIT FFT over smem ----------
// data bit-reverse permuted on input; both data and tw stored with PADI layout.
__device__ __forceinline__ void fft_fused(float2* a, const float2* tw,
                                          int n, int logn, float sign,
                                          int tid, int T) {
    int st = 1;
    if (logn & 1) {                      // one plain radix-2 stage (w = 1)
        int nb = n >> 1;
        for (int idx = tid; idx < nb; idx += T) {
            int i0 = idx << 1;
            int p0 = PADI(i0), p1 = PADI(i0 + 1);
            float2 u = a[p0], v = a[p1];
            a[p0] = make_float2(u.x + v.x, u.y + v.y);
            a[p1] = make_float2(u.x - v.x, u.y - v.y);
        }
        __syncthreads();
        st = 2;
    }
    int nq = n >> 2;
    for (; st < logn; st += 2) {
        int h = 1 << (st - 1);
        int shift = logn - st;           // >= 1
        for (int q = tid; q < nq; q += T) {
            int jj = q & (h - 1);
            int i0 = ((q >> (st - 1)) << (st + 1)) + jj;
            int p0 = PADI(i0), p1 = PADI(i0 + h);
            int p2 = PADI(i0 + 2 * h), p3 = PADI(i0 + 3 * h);
            float2 x0 = a[p0], x1 = a[p1], x2 = a[p2], x3 = a[p3];
            float2 wa = tw[PADI(jj << shift)];
            float2 wb = tw[PADI(jj << (shift - 1))];
            float2 t1 = cmul_s(x1, wa, sign);
            float2 t3 = cmul_s(x3, wa, sign);
            float2 y0 = make_float2(x0.x + t1.x, x0.y + t1.y);
            float2 y1 = make_float2(x0.x - t1.x, x0.y - t1.y);
            float2 y2 = make_float2(x2.x + t3.x, x2.y + t3.y);
            float2 y3 = make_float2(x2.x - t3.x, x2.y - t3.y);
            float2 u2 = cmul_s(y2, wb, sign);
            float2 u3 = cmul_s(y3, wb, sign);
            float2 v3 = make_float2(-sign * u3.y, sign * u3.x); // wc = i*sign*wb
            a[p0] = make_float2(y0.x + u2.x, y0.y + u2.y);
            a[p2] = make_float2(y0.x - u2.x, y0.y - u2.y);
            a[p1] = make_float2(y1.x + v3.x, y1.y + v3.y);
            a[p3] = make_float2(y1.x - v3.x, y1.y - v3.y);
        }
        __syncthreads();
    }
}

__device__ __forceinline__ void build_twiddles(float2* tw, int n, int tid, int T) {
    for (int r = tid; r < (n >> 1); r += T) {
        float s_, c_;
        sincospif(2.0f * (float)r / (float)n, &s_, &c_);
        tw[PADI(r)] = make_float2(c_, s_);
    }
}

// ---------------- 1) forward rfft of each 32768-sample signal -----------------
extern __shared__ float2 smem_c[];
#define DATA_PAD 17472      // PADI(16383)+1 rounded

__global__ __launch_bounds__(1024) void fwd_fft_kernel(const float* __restrict__ tgt,
                                                       const float* __restrict__ rec) {
    const int m = 16384, logm = 14;
    int sig = blockIdx.x;
    const float* x = (sig < 8) ? (tgt + (size_t)sig * NSAMP)
                               : (rec + (size_t)(sig - 8) * NSAMP);
    float2* data = smem_c;
    float2* tw   = smem_c + DATA_PAD;
    int tid = threadIdx.x, T = blockDim.x;

    build_twiddles(tw, m, tid, T);
    for (int t = tid; t < m; t += T) {
        int r = (int)(__brev((unsigned)t) >> (32 - logm));
        data[PADI(r)] = make_float2(x[2 * t], x[2 * t + 1]);
    }
    __syncthreads();
    fft_fused(data, tw, m, logm, -1.0f, tid, T);

    for (int k = tid; k < m; k += T) {
        float2 zk = data[PADI(k)];
        float2 zm = data[PADI((m - k) & (m - 1))];
        float2 E = make_float2(0.5f * (zk.x + zm.x), 0.5f * (zk.y - zm.y));
        float2 D = make_float2(0.5f * (zk.x - zm.x), 0.5f * (zk.y + zm.y));
        float s_, c_;
        sincospif(-2.0f * (float)k / (float)NSAMP, &s_, &c_);
        float2 miD = make_float2(D.y, -D.x);
        float tr = miD.x * c_ - miD.y * s_;
        float ti = miD.x * s_ + miD.y * c_;
        d_X[sig * 16384 + k] = make_float2(E.x + tr, E.y + ti);
    }
}

// ---------------- 2) per-band inverse rfft (ortho-scaled) ---------------------
__global__ __launch_bounds__(1024) void inv_band_kernel() {
    int j   = blockIdx.x;
    int sig = blockIdx.y;
    int m = 256 << j, logm = 8 + j;
    int lo = (j == 0) ? 0 : (m >> 1);
    int s2 = 2 * m;
    const float2* X = d_X + sig * 16384;
    float2* data = smem_c;
    float2* tw   = smem_c + DATA_PAD;
    int tid = threadIdx.x, T = blockDim.x;

    build_twiddles(tw, m, tid, T);
    for (int k = tid; k < m; k += T) {
        float2 Xk = (k >= lo) ? X[k] : make_float2(0.f, 0.f);
        int mk = m - k;
        float2 Xm = (mk >= lo && mk < m) ? X[mk] : make_float2(0.f, 0.f);
        float2 E = make_float2(0.5f * (Xk.x + Xm.x), 0.5f * (Xk.y - Xm.y));
        float2 D = make_float2(0.5f * (Xk.x - Xm.x), 0.5f * (Xk.y + Xm.y));
        float s_, c_;
        sincospif(2.0f * (float)k / (float)s2, &s_, &c_);
        float2 O = make_float2(D.x * c_ - D.y * s_, D.x * s_ + D.y * c_);
        float2 Z = make_float2(E.x - O.y, E.y + O.x);
        int r = (int)(__brev((unsigned)k) >> (32 - logm));
        data[PADI(r)] = Z;
    }
    __syncthreads();
    fft_fused(data, tw, m, logm, +1.0f, tid, T);

    float scale = 2.0f * rsqrtf((float)s2 * (float)NSAMP);
    float* out = d_band + sig * BAND_SPAN + band_off(j);
    for (int t = tid; t < m; t += T) {
        float2 z = data[PADI(t)];
        out[2 * t]     = scale * z.x;
        out[2 * t + 1] = scale * z.y;
    }
}

// ---------------- 3) 64-tap FIR + segment maxima, packed f32x2 ----------------
#define FMA2(acc, a, b) asm("fma.rn.f32x2 %0, %1, %2, %3;" \
    : "=l"(acc) : "l"(a), "l"(b), "l"(acc))

template<int P>
__device__ __forceinline__ float conv_block(const unsigned long long* __restrict__ tilU,
                                            const unsigned long long* __restrict__ frowU,
                                            int rel, int base, int s) {
    unsigned long long W[P + 1], S[P], T[P + 1];
#pragma unroll
    for (int m = 0; m <= P; m++) W[m] = tilU[rel - 1 + m];
#pragma unroll
    for (int p = 0; p < P; p++) S[p] = 0ull;
#pragma unroll
    for (int p = 0; p <= P; p++) T[p] = 0ull;
#pragma unroll
    for (int h = 0; h < 32; h++) {
        unsigned long long te = frowU[2 * h];
        unsigned long long to = frowU[2 * h + 1];
#pragma unroll
        for (int p = 0; p < P; p++) FMA2(S[p], W[p + 1], te);
#pragma unroll
        for (int p = 0; p <= P; p++) FMA2(T[p], W[p], to);
        if (h < 31) {
#pragma unroll
            for (int m = P; m >= 1; m--) W[m] = W[m - 1];
            W[0] = tilU[rel - h - 2];
        }
    }
    float mx = -INFINITY;
#pragma unroll
    for (int p = 0; p < P; p++) {
        float2 sv = *(float2*)&S[p];
        float2 ta = *(float2*)&T[p];
        float2 tb = *(float2*)&T[p + 1];
        float v0 = sv.x + ta.y;        // out[base+2p]
        float v1 = sv.y + tb.x;        // out[base+2p+1]
        int ia = base + 2 * p;
        if (ia < 0 || ia >= s)         v0 = -INFINITY;
        if (ia + 1 < 0 || ia + 1 >= s) v1 = -INFINITY;
        mx = fmaxf(mx, fmaxf(v0, v1));
    }
    return mx;
}

// max over 'cnt' conv outputs starting at output offset o0 (from i0)
__device__ __forceinline__ float conv_run(const unsigned long long* __restrict__ tilU,
                                          const unsigned long long* __restrict__ frowU,
                                          int i0, int o0, int cnt, int s) {
    int rel  = (o0 >> 1) + 32;
    int base = i0 + o0;
    if (cnt == 2)  return conv_block<1>(tilU, frowU, rel, base, s);
    if (cnt == 4)  return conv_block<2>(tilU, frowU, rel, base, s);
    if (cnt == 8)  return conv_block<4>(tilU, frowU, rel, base, s);
    float mx = -INFINITY;
    int nb = cnt >> 4;
    for (int b = 0; b < nb; b++)
        mx = fmaxf(mx, conv_block<8>(tilU, frowU, rel + 8 * b, base + 16 * b, s));
    return mx;
}

__global__ __launch_bounds__(256) void conv_seg_kernel(const float* __restrict__ filters) {
    int chunk = blockIdx.x;
    int j     = blockIdx.y;
    int sig   = blockIdx.z;
    int c = 64 >> j; if (c < 1) c = 1;           // segments per chunk
    int nchunk = (65 + c - 1) / c;
    if (chunk >= nchunk) return;
    int q0 = chunk * c;
    int qn = 65 - q0; if (qn > c) qn = c;

    int stride = 8 << j;
    int s = 512 << j;
    int pad = stride >> 1;
    int i0 = q0 * stride - pad;
    int nout = qn * stride;
    const float* band = d_band + sig * BAND_SPAN + band_off(j);

    __shared__ float2 tile2[292];
    __shared__ float2 filt2[64 * 65];
    __shared__ float red[4][64];

    int tid = threadIdx.x;
    int tstart2 = i0 - 64;                       // even
    int tlen2 = (nout + 64) >> 1;
    for (int m = tid; m < tlen2; m += 256) {
        int g = tstart2 + 2 * m;
        float a = (g >= 0 && g < s)         ? band[g]     : 0.0f;
        float b = (g + 1 >= 0 && g + 1 < s) ? band[g + 1] : 0.0f;
        tile2[m] = make_float2(a, b);
    }
    for (int t = tid; t < 4096; t += 256) {
        float v = filters[t];
        filt2[(t >> 6) * 65 + (t & 63)] = make_float2(v, v);
    }
    __syncthreads();

    int f = tid & 63, grp = tid >> 6;
    const unsigned long long* tilU  = (const unsigned long long*)tile2;
    const unsigned long long* frowU = (const unsigned long long*)(filt2 + f * 65);
    float* segout = d_seg + (size_t)((sig * NBANDS + j) * NFILT + f) * 65;

    if (qn >= 4) {
        // each group owns whole segments; no cross-group reduction
        for (int q = grp; q < qn; q += 4) {
            float mx = conv_run(tilU, frowU, i0, q * stride, stride, s);
            segout[q0 + q] = mx;
        }
    } else {
        // qn == 1 or 2: split segment(s) across groups, reduce in smem
        int opg = (qn * stride) >> 2;
        float mx = conv_run(tilU, frowU, i0, grp * opg, opg, s);
        red[grp][f] = mx;
        __syncthreads();
        if (qn == 1) {
            if (tid < 64) {
                float v = fmaxf(fmaxf(red[0][tid], red[1][tid]),
                                fmaxf(red[2][tid], red[3][tid]));
                segout[q0] = v;   // careful: segout uses f=tid here since tid<64
            }
        } else {  // qn == 2: groups {0,1} -> seg q0, {2,3} -> seg q0+1
            if ((grp & 1) == 0) {
                float v = fmaxf(red[grp][f], red[grp | 1][f]);
                segout[q0 + (grp >> 1)] = v;
            }
        }
    }
}

// ---------------- 4) exact top-128 via radix-select + small bitonic -----------
__global__ __launch_bounds__(256) void topk_kernel() {
    int j   = blockIdx.x;
    int sig = blockIdx.y;
    __shared__ unsigned hk[4096];
    __shared__ int hist[4096];
    __shared__ unsigned long long cand[1024];
    __shared__ int scanbuf[256];
    __shared__ int s_b1, s_count;
    const float* seg = d_seg + (size_t)(sig * NBANDS + j) * NFILT * 65;
    int tid = threadIdx.x;

    for (int t = tid; t < 4096; t += 256) {
        int f = t >> 6, o = t & 63;
        float v = fmaxf(seg[f * 65 + o], seg[f * 65 + o + 1]);
        unsigned ub = __float_as_uint(v);
        ub = (ub >> 31) ? ~ub : (ub | 0x80000000u);
        hk[t] = ~ub;
        hist[t] = 0;
    }
    if (tid == 0) s_count = 0;
    __syncthreads();
    for (int t = tid; t < 4096; t += 256)
        atomicAdd(&hist[hk[t] >> 20], 1);
    __syncthreads();

    int part = 0;
#pragma unroll
    for (int i = 0; i < 16; i++) part += hist[tid * 16 + i];
    scanbuf[tid] = part;
    __syncthreads();
    for (int off = 1; off < 256; off <<= 1) {
        int v = (tid >= off) ? scanbuf[tid - off] : 0;
        __syncthreads();
        scanbuf[tid] += v;
        __syncthreads();
    }
    int incl = scanbuf[tid];
    int excl = (tid > 0) ? scanbuf[tid - 1] : 0;
    if (incl >= KTOP && excl < KTOP) {
        int cum = excl;
        for (int i = 0; i < 16; i++) {
            int cc = hist[tid * 16 + i];
            if (cum + cc >= KTOP) { s_b1 = tid * 16 + i; break; }
            cum += cc;
        }
    }
    __syncthreads();
    unsigned b1 = (unsigned)s_b1;

    for (int t = tid; t < 4096; t += 256) {
        if ((hk[t] >> 20) <= b1) {
            int pos = atomicAdd(&s_count, 1);
            if (pos < 1024)
                cand[pos] = ((unsigned long long)hk[t] << 32) | (unsigned)t;
        }
    }
    __syncthreads();
    int n = s_count < 1024 ? s_count : 1024;
    for (int t = tid; t < 1024; t += 256)
        if (t >= n) cand[t] = ~0ull;
    __syncthreads();

    int nsort = (n <= 256) ? 256 : 1024;
    for (int kk = 2; kk <= nsort; kk <<= 1) {
        for (int jj = kk >> 1; jj > 0; jj >>= 1) {
            for (int v = tid; v < nsort; v += 256) {
                int ixj = v ^ jj;
                if (ixj > v) {
                    bool up = ((v & kk) == 0);
                    unsigned long long A = cand[v], B = cand[ixj];
                    if (up ? (A > B) : (A < B)) { cand[v] = B; cand[ixj] = A; }
                }
            }
            __syncthreads();
        }
    }
    if (tid < KTOP) {
        unsigned long long key = cand[tid];
        int idx = (int)(unsigned)key;
        int f = idx >> 6, o = idx & 63;
        float v = fmaxf(seg[f * 65 + o], seg[f * 65 + o + 1]);
        int base = (sig * NBANDS + j) * KTOP + tid;
        d_tkv[base] = v;
        d_tki[base] = idx;
    }
}

// ---------------- 5) loss ------------------------------------------------------
__global__ __launch_bounds__(128) void loss_kernel(const float* __restrict__ PT,
                                                   const float* __restrict__ PF) {
    int b = blockIdx.x;
    int j = blockIdx.y;
    int k = threadIdx.x;
    int ti = (b * NBANDS + j) * KTOP + k;
    int ri = ((b + 8) * NBANDS + j) * KTOP + k;
    float vt = d_tkv[ti]; int it = d_tki[ti];
    float vr = d_tkv[ri]; int ir = d_tki[ri];
    int tmt = it & 63, cht = it >> 6;
    int tmr = ir & 63, chr_ = ir >> 6;
    const float* ptt  = PT + tmt * 128;
    const float* ptr_ = PT + tmr * 128;
    const float* pft  = PF + cht * 128;
    const float* pfr  = PF + chr_ * 128;
    float ssum = 0.0f;
#pragma unroll 4
    for (int d = 0; d < 128; d++) {
        ssum += fabsf(vt * ptt[d] - vr * ptr_[d]);
        ssum += fabsf(pft[d] - pfr[d]);
    }
    __shared__ float rs[128];
    rs[k] = ssum;
    __syncthreads();
    for (int st = 64; st > 0; st >>= 1) {
        if (k < st) rs[k] += rs[k + st];
        __syncthreads();
    }
    if (k == 0) d_partial[b * NBANDS + j] = rs[0];
}

__global__ void final_kernel(float* out) {
    if (threadIdx.x == 0) {
        float s = 0.0f;
        for (int i = 0; i < PBLOCKS; i++) s += d_partial[i];
        out[0] = s / 1835008.0f;   // 8 * 128 * 256 * 7
    }
}

// ---------------- launch ------------------------------------------------------
extern "C" void kernel_launch(void* const* d_in, const int* in_sizes, int n_in,
                              void* d_out, int out_size) {
    const float* target  = (const float*)d_in[0];
    const float* recon   = (const float*)d_in[1];
    const float* filters = (const float*)d_in[2];
    const float* PT      = (const float*)d_in[3];
    const float* PF      = (const float*)d_in[4];
    float* out = (float*)d_out;

    // data (padded 16384) + twiddles (padded 8192)
    const int FFT_SMEM = (DATA_PAD + 8736) * sizeof(float2);   // 209664 B
    cudaFuncSetAttribute(fwd_fft_kernel,
                         cudaFuncAttributeMaxDynamicSharedMemorySize, FFT_SMEM);
    cudaFuncSetAttribute(inv_band_kernel,
                         cudaFuncAttributeMaxDynamicSharedMemorySize, FFT_SMEM);

    fwd_fft_kernel<<<NSIG, 1024, FFT_SMEM>>>(target, recon);
    inv_band_kernel<<<dim3(NBANDS, NSIG), 1024, FFT_SMEM>>>();
    conv_seg_kernel<<<dim3(65, NBANDS, NSIG), 256>>>(filters);
    topk_kernel<<<dim3(NBANDS, NSIG), 256>>>();
    loss_kernel<<<dim3(8, NBANDS), 128>>>(PT, PF);
    final_kernel<<<1, 32>>>(out);
}